// round 2
// baseline (speedup 1.0000x reference)
#include <cuda_runtime.h>
#include <cstdint>

// Problem constants (shapes fixed by the benchmark)
#define NIMG   64
#define KDET   300
#define NCLS   80
#define CPERA  85          // 5 + 80 features per anchor
#define HW13   169
#define HW26   676
#define HW52   2704
#define NB13   (HW13*3)    // 507
#define NB26   (HW26*3)    // 2028
#define NB52   (HW52*3)    // 8112
#define OFF13  0
#define OFF26  NB13        // 507
#define OFF52  (NB13+NB26) // 2535
#define NTOT   (NB13+NB26+NB52)  // 10647
#define VCAP   1024        // capacity for valid (conf>thresh) boxes per image
#define BMW    333         // bitmap words: ceil(10647/32)

// ---------------- scratch (no allocations allowed) ----------------
__device__ int   g_topi[NIMG * KDET];
__device__ float g_sel [NIMG * KDET * 10]; // conf,ox,oy,w,h,cls,x1,y1,x2,y2
__device__ int   g_val [NIMG * KDET];

// ---------------- K1: per-image valid-compaction + sort + pad ----------------
__device__ __forceinline__ unsigned f2ord(float f) {
    unsigned u = __float_as_uint(f);
    return (u & 0x80000000u) ? ~u : (u | 0x80000000u);
}

__global__ void topk_kernel(const float* __restrict__ o13,
                            const float* __restrict__ o26,
                            const float* __restrict__ o52,
                            const float* __restrict__ thr_p)
{
    __shared__ unsigned           s_bm[BMW];
    __shared__ unsigned long long s_keys[VCAP];
    __shared__ int                s_cnt;

    const int n   = blockIdx.x;
    const int tid = threadIdx.x;
    const int nt  = blockDim.x;

    if (tid == 0) s_cnt = 0;
    for (int i = tid; i < BMW; i += nt) s_bm[i] = 0u;
    __syncthreads();

    const float thr = *thr_p;

    // scan conf channels of the 3 scales (coalesced over spatial dim)
    {
        const float* ptrs[3] = {o13, o26, o52};
        const int    hws [3] = {HW13, HW26, HW52};
        const int    offs[3] = {OFF13, OFF26, OFF52};
        #pragma unroll
        for (int s = 0; s < 3; s++) {
            const float* o  = ptrs[s];
            const int    HW = hws[s];
            for (int a = 0; a < 3; a++) {
                const float* base = o + ((size_t)n * 255 + a * CPERA) * HW;
                for (int p = tid; p < HW; p += nt) {
                    float c = base[p];
                    if (c > thr) {
                        int g = offs[s] + p * 3 + a;    // box index in concat order
                        unsigned long long key =
                            ((unsigned long long)f2ord(c) << 32) |
                            (unsigned long long)(0xFFFFFFFFu - (unsigned)g);
                        int pos = atomicAdd(&s_cnt, 1);
                        if (pos < VCAP) s_keys[pos] = key;
                        atomicOr(&s_bm[g >> 5], 1u << (g & 31));
                    }
                }
            }
        }
    }
    __syncthreads();

    int nv = s_cnt; if (nv > VCAP) nv = VCAP;

    // bitonic sort descending over next-pow2(nv)
    int M = 1; while (M < nv) M <<= 1; if (M < 2) M = 2;
    for (int i = tid; i < M; i += nt) if (i >= nv) s_keys[i] = 0ULL;
    __syncthreads();
    for (int k = 2; k <= M; k <<= 1) {
        for (int j = k >> 1; j > 0; j >>= 1) {
            for (int i = tid; i < M; i += nt) {
                int l = i ^ j;
                if (l > i) {
                    unsigned long long a = s_keys[i], b = s_keys[l];
                    bool descSeg = ((i & k) == 0);
                    if (descSeg ? (a < b) : (a > b)) { s_keys[i] = b; s_keys[l] = a; }
                }
            }
            __syncthreads();
        }
    }

    const int take = (nv < KDET) ? nv : KDET;
    for (int kk = tid; kk < take; kk += nt)
        g_topi[n * KDET + kk] = 0xFFFFFFFFu - (unsigned)(s_keys[kk] & 0xFFFFFFFFu);

    // pad with smallest invalid indices (jax top_k tie rule on -inf)
    if (tid == 0 && take < KDET) {
        int idx = 0;
        for (int kk = take; kk < KDET; kk++) {
            while ((s_bm[idx >> 5] >> (idx & 31)) & 1u) idx++;
            g_topi[n * KDET + kk] = idx;
            idx++;
        }
    }
}

// ---------------- K2: decode only the selected 300/image ----------------
__global__ void decode_kernel(const float* __restrict__ o13,
                              const float* __restrict__ o26,
                              const float* __restrict__ o52,
                              const float* __restrict__ a13,
                              const float* __restrict__ a26,
                              const float* __restrict__ a52,
                              const float* __restrict__ thr_p)
{
    int t = blockIdx.x * blockDim.x + threadIdx.x;
    if (t >= NIMG * KDET) return;
    const int n = t / KDET;
    const int g = g_topi[t];

    const float* o; const float* anch;
    int HW, W, bi; float stride;
    if (g < OFF26)      { o = o13; HW = HW13; W = 13; stride = 32.f; anch = a13; bi = g; }
    else if (g < OFF52) { o = o26; HW = HW26; W = 26; stride = 16.f; anch = a26; bi = g - OFF26; }
    else                { o = o52; HW = HW52; W = 52; stride =  8.f; anch = a52; bi = g - OFF52; }

    const int a = bi % 3;
    const int p = bi / 3;
    const int y = p / W;
    const int x = p - y * W;

    const float* base = o + ((size_t)n * 255 + a * CPERA) * HW + p;
    const float conf = base[0];
    const float tx = base[1 * HW];
    const float ty = base[2 * HW];
    const float tw = base[3 * HW];
    const float th = base[4 * HW];

    const float ox = ((float)x + tx) * stride;
    const float oy = ((float)y + ty) * stride;
    const float w  = expf(tw) * anch[a * 2 + 0];
    const float h  = expf(th) * anch[a * 2 + 1];

    float best = base[5 * HW];
    int cls = 0;
    #pragma unroll 4
    for (int c = 1; c < NCLS; c++) {
        float v = base[(5 + c) * HW];
        if (v > best) { best = v; cls = c; }   // strict > : first max wins (jax argmax)
    }

    float* s = &g_sel[(size_t)t * 10];
    s[0] = conf; s[1] = ox; s[2] = oy; s[3] = w; s[4] = h; s[5] = (float)cls;
    s[6] = ox - w * 0.5f; s[7] = oy - h * 0.5f;
    s[8] = ox + w * 0.5f; s[9] = oy + h * 0.5f;
    g_val[t] = (conf > *thr_p) ? 1 : 0;
}

// ---------------- K3: warp-per-image sequential NMS + output ----------------
__global__ void nms_kernel(float* __restrict__ out)
{
    const int n    = blockIdx.x;
    const int lane = threadIdx.x;   // 32 threads

    __shared__ float sx1[KDET], sy1[KDET], sx2[KDET], sy2[KDET];
    __shared__ float scl[KDET], sar[KDET];
    __shared__ unsigned char skeep[KDET], sval[KDET];

    for (int k = lane; k < KDET; k += 32) {
        const float* s = &g_sel[(size_t)(n * KDET + k) * 10];
        float x1 = s[6], y1 = s[7], x2 = s[8], y2 = s[9];
        sx1[k] = x1; sy1[k] = y1; sx2[k] = x2; sy2[k] = y2;
        scl[k] = s[5];
        sar[k] = (x2 - x1) * (y2 - y1);
        sval[k] = (unsigned char)g_val[n * KDET + k];
        skeep[k] = 0;
    }
    __syncwarp();

    for (int i = 0; i < KDET; i++) {
        const bool v = (sval[i] != 0);   // uniform across warp
        bool sup = false;
        if (v) {
            bool mine = false;
            const float x1 = sx1[i], y1 = sy1[i], x2 = sx2[i], y2 = sy2[i];
            const float ar = sar[i], cl = scl[i];
            for (int j = lane; j < i; j += 32) {
                if (skeep[j] && scl[j] == cl) {
                    float ix1 = fmaxf(x1, sx1[j]);
                    float iy1 = fmaxf(y1, sy1[j]);
                    float ix2 = fminf(x2, sx2[j]);
                    float iy2 = fminf(y2, sy2[j]);
                    float iw = fmaxf(ix2 - ix1, 0.f);
                    float ih = fmaxf(iy2 - iy1, 0.f);
                    float inter = iw * ih;
                    float uni = ar + sar[j] - inter;
                    float iou = inter / fmaxf(uni, 1e-9f);
                    if (iou > 0.3f) mine = true;
                }
            }
            sup = __any_sync(0xFFFFFFFFu, mine);
        }
        if (lane == 0) skeep[i] = (v && !sup) ? 1 : 0;
        __syncwarp();
    }

    for (int k = lane; k < KDET; k += 32) {
        float* o = out + (size_t)(n * KDET + k) * 7;
        if (skeep[k]) {
            const float* s = &g_sel[(size_t)(n * KDET + k) * 10];
            o[0] = s[0]; o[1] = s[1]; o[2] = s[2];
            o[3] = s[3]; o[4] = s[4]; o[5] = s[5];
            o[6] = (float)n;
        } else {
            #pragma unroll
            for (int c = 0; c < 7; c++) o[c] = 0.f;
        }
    }
}

// ---------------- launch ----------------
extern "C" void kernel_launch(void* const* d_in, const int* in_sizes, int n_in,
                              void* d_out, int out_size)
{
    const float* o13 = (const float*)d_in[0];
    const float* o26 = (const float*)d_in[1];
    const float* o52 = (const float*)d_in[2];
    const float* a13 = (const float*)d_in[3];
    const float* a26 = (const float*)d_in[4];
    const float* a52 = (const float*)d_in[5];
    const float* thr = (const float*)d_in[6];
    float* out = (float*)d_out;

    topk_kernel<<<NIMG, 1024>>>(o13, o26, o52, thr);

    const int total = NIMG * KDET;
    decode_kernel<<<(total + 255) / 256, 256>>>(o13, o26, o52, a13, a26, a52, thr);

    nms_kernel<<<NIMG, 32>>>(out);
}

// round 6
// speedup vs baseline: 3.1403x; 3.1403x over previous
#include <cuda_runtime.h>
#include <cstdint>

#define NIMG   64
#define KDET   300
#define NCLS   80
#define HW13   169
#define HW26   676
#define HW52   2704
#define NB13   (HW13*3)
#define NB26   (HW26*3)
#define NB52   (HW52*3)
#define OFF13  0
#define OFF26  NB13
#define OFF52  (NB13+NB26)
#define NTOT   (NB13+NB26+NB52)   // 10647
#define VCAP   1024
#define BMW    333                // ceil(10647/32)
#define NT     1024

__device__ __forceinline__ unsigned f2ord(float f) {
    unsigned u = __float_as_uint(f);
    return (u & 0x80000000u) ? ~u : (u | 0x80000000u);
}

// conf-channel scan for one scale: appends keys for conf>thr, sets bitmap
template<int HW, int OFF>
__device__ __forceinline__ void scan_scale(const float* __restrict__ o, int n, float thr,
                                           int tid, unsigned* s_bm,
                                           unsigned long long* s_keys, int* s_cnt)
{
    const float* base = o + (size_t)n * 255 * HW;
    #pragma unroll 1
    for (int idx = tid; idx < 3 * HW; idx += NT) {
        const int a  = idx / HW;          // constant HW -> cheap
        const int pp = idx - a * HW;
        float c = base[a * 85 * HW + pp];
        if (c > thr) {
            int g = OFF + pp * 3 + a;
            unsigned long long key =
                ((unsigned long long)f2ord(c) << 32) |
                (unsigned long long)(0xFFFFFFFFu - (unsigned)g);
            int pos = atomicAdd(s_cnt, 1);
            if (pos < VCAP) s_keys[pos] = key;
            atomicOr(&s_bm[g >> 5], 1u << (g & 31));
        }
    }
}

__global__ __launch_bounds__(NT, 1)
void detect_fused_kernel(const float* __restrict__ o13,
                         const float* __restrict__ o26,
                         const float* __restrict__ o52,
                         const float* __restrict__ a13,
                         const float* __restrict__ a26,
                         const float* __restrict__ a52,
                         const float* __restrict__ thr_p,
                         float* __restrict__ out)
{
    __shared__ unsigned           s_bm[BMW];
    __shared__ int                s_cnt;
    __shared__ unsigned long long s_keys[VCAP];
    __shared__ int                s_gidx[KDET];
    __shared__ int                s_pc[BMW];
    __shared__ float s_conf[KDET], s_ox[KDET], s_oy[KDET], s_w[KDET], s_h[KDET];
    __shared__ float s_cls[KDET], s_x1[KDET], s_y1[KDET], s_x2[KDET], s_y2[KDET], s_ar[KDET];
    __shared__ unsigned char s_keep[KDET];

    const int n    = blockIdx.x;
    const int tid  = threadIdx.x;
    const int wid  = tid >> 5;
    const int lane = tid & 31;

    if (tid == 0) s_cnt = 0;
    for (int i = tid; i < BMW; i += NT) s_bm[i] = 0u;
    for (int k = tid; k < KDET; k += NT) s_keep[k] = 0;
    __syncthreads();

    const float thr = *thr_p;

    // ---- phase 1: conf scan + compact ----
    scan_scale<HW13, OFF13>(o13, n, thr, tid, s_bm, s_keys, &s_cnt);
    scan_scale<HW26, OFF26>(o26, n, thr, tid, s_bm, s_keys, &s_cnt);
    scan_scale<HW52, OFF52>(o52, n, thr, tid, s_bm, s_keys, &s_cnt);
    __syncthreads();

    int nv = s_cnt; if (nv > VCAP) nv = VCAP;
    const int take = (nv < KDET) ? nv : KDET;

    // ---- phase 2: rank sort (keys distinct by construction) ----
    if (tid < nv) {
        unsigned long long key = s_keys[tid];
        int rank = 0;
        for (int j = 0; j < nv; j++) rank += (s_keys[j] > key);
        if (rank < KDET)
            s_gidx[rank] = (int)(0xFFFFFFFFu - (unsigned)(key & 0xFFFFFFFFu));
    }

    // ---- phase 3: padding with smallest invalid indices (parallel bitmap rank) ----
    for (int i = tid; i < BMW; i += NT) s_pc[i] = __popc(s_bm[i]);
    __syncthreads();
    if (tid == 0) {                 // exclusive prefix over 333 words
        int run = 0;
        for (int w = 0; w < BMW; w++) { int t = s_pc[w]; s_pc[w] = run; run += t; }
    }
    __syncthreads();
    const int need = KDET - take;
    if (need > 0) {
        int limit = KDET + nv; if (limit > NTOT) limit = NTOT;
        for (int idx = tid; idx < limit; idx += NT) {
            unsigned w = s_bm[idx >> 5], bit = 1u << (idx & 31);
            if (!(w & bit)) {
                int rank = idx - (s_pc[idx >> 5] + __popc(w & (bit - 1)));
                if (rank < need) s_gidx[take + rank] = idx;
            }
        }
    }
    __syncthreads();

    // ---- phase 4: decode ONLY the `take` valid entries (warp per entry) ----
    for (int k = wid; k < take; k += (NT / 32)) {
        const int g = s_gidx[k];
        const float* o; const float* anch; int HW, W, bi; float stride;
        if (g < OFF26)      { o = o13; HW = HW13; W = 13; stride = 32.f; anch = a13; bi = g; }
        else if (g < OFF52) { o = o26; HW = HW26; W = 26; stride = 16.f; anch = a26; bi = g - OFF26; }
        else                { o = o52; HW = HW52; W = 52; stride =  8.f; anch = a52; bi = g - OFF52; }
        const int a = bi % 3;
        const int p = bi / 3;
        const int y = p / W;
        const int x = p - y * W;
        const float* base = o + ((size_t)n * 255 + a * 85) * HW + p;

        // head: lanes 0..4 load conf,tx,ty,tw,th
        float head = (lane < 5) ? base[lane * HW] : 0.f;

        // class argmax (first-max-wins): lane-strided then shuffle reduce
        float best = -3.402823466e+38f; int bc = 0;
        for (int c = lane; c < NCLS; c += 32) {
            float v = base[(5 + c) * HW];
            if (v > best) { best = v; bc = c; }
        }
        #pragma unroll
        for (int off = 16; off > 0; off >>= 1) {
            float vb = __shfl_down_sync(0xFFFFFFFFu, best, off);
            int   cb = __shfl_down_sync(0xFFFFFFFFu, bc,   off);
            if (vb > best || (vb == best && cb < bc)) { best = vb; bc = cb; }
        }

        const float conf = __shfl_sync(0xFFFFFFFFu, head, 0);
        const float tx   = __shfl_sync(0xFFFFFFFFu, head, 1);
        const float ty   = __shfl_sync(0xFFFFFFFFu, head, 2);
        const float tw   = __shfl_sync(0xFFFFFFFFu, head, 3);
        const float th   = __shfl_sync(0xFFFFFFFFu, head, 4);

        if (lane == 0) {
            const float ox = ((float)x + tx) * stride;
            const float oy = ((float)y + ty) * stride;
            const float w  = __expf(tw) * anch[a * 2 + 0];
            const float h  = __expf(th) * anch[a * 2 + 1];
            s_conf[k] = conf; s_ox[k] = ox; s_oy[k] = oy;
            s_w[k] = w; s_h[k] = h; s_cls[k] = (float)bc;
            const float x1 = ox - w * 0.5f, y1 = oy - h * 0.5f;
            const float x2 = ox + w * 0.5f, y2 = oy + h * 0.5f;
            s_x1[k] = x1; s_y1[k] = y1; s_x2[k] = x2; s_y2[k] = y2;
            s_ar[k] = (x2 - x1) * (y2 - y1);
        }
    }
    __syncthreads();

    // ---- phase 5: sequential NMS over the `take` valid entries (warp 0) ----
    if (wid == 0) {
        for (int i = 0; i < take; i++) {
            bool mine = false;
            const float x1 = s_x1[i], y1 = s_y1[i], x2 = s_x2[i], y2 = s_y2[i];
            const float ar = s_ar[i], cl = s_cls[i];
            for (int j = lane; j < i; j += 32) {
                if (s_keep[j] && s_cls[j] == cl) {
                    float iw = fminf(x2, s_x2[j]) - fmaxf(x1, s_x1[j]);
                    float ih = fminf(y2, s_y2[j]) - fmaxf(y1, s_y1[j]);
                    float inter = fmaxf(iw, 0.f) * fmaxf(ih, 0.f);
                    float uni = ar + s_ar[j] - inter;
                    if (inter / fmaxf(uni, 1e-9f) > 0.3f) mine = true;
                }
            }
            bool sup = __any_sync(0xFFFFFFFFu, mine);
            if (lane == 0) s_keep[i] = sup ? 0 : 1;
            __syncwarp();
        }
    }
    __syncthreads();

    // ---- phase 6: coalesced output (7 floats per detection) ----
    float* outn = out + (size_t)n * KDET * 7;
    for (int j = tid; j < KDET * 7; j += NT) {
        const int k = j / 7, c = j - k * 7;
        float v = 0.f;
        if (s_keep[k]) {
            switch (c) {
                case 0: v = s_conf[k]; break;
                case 1: v = s_ox[k];   break;
                case 2: v = s_oy[k];   break;
                case 3: v = s_w[k];    break;
                case 4: v = s_h[k];    break;
                case 5: v = s_cls[k];  break;
                default: v = (float)n; break;
            }
        }
        outn[j] = v;
    }
}

extern "C" void kernel_launch(void* const* d_in, const int* in_sizes, int n_in,
                              void* d_out, int out_size)
{
    const float* o13 = (const float*)d_in[0];
    const float* o26 = (const float*)d_in[1];
    const float* o52 = (const float*)d_in[2];
    const float* a13 = (const float*)d_in[3];
    const float* a26 = (const float*)d_in[4];
    const float* a52 = (const float*)d_in[5];
    const float* thr = (const float*)d_in[6];
    float* out = (float*)d_out;

    detect_fused_kernel<<<NIMG, NT>>>(o13, o26, o52, a13, a26, a52, thr, out);
}

// round 10
// speedup vs baseline: 6.8250x; 2.1733x over previous
#include <cuda_runtime.h>
#include <cstdint>

#define NIMG   64
#define KDET   300
#define NCLS   80
#define HW13   169
#define HW26   676
#define HW52   2704
#define NB13   (HW13*3)
#define NB26   (HW26*3)
#define NB52   (HW52*3)
#define OFF13  0
#define OFF26  NB13
#define OFF52  (NB13+NB26)
#define NTOT   (NB13+NB26+NB52)   // 10647
#define VCAP   1024
#define BMW    333                // ceil(10647/32)
#define NT     1024
#define RMAX   10                 // ceil(KDET/32) words per sup row

__device__ __forceinline__ unsigned f2ord(float f) {
    unsigned u = __float_as_uint(f);
    return (u & 0x80000000u) ? ~u : (u | 0x80000000u);
}

__global__ __launch_bounds__(NT, 1)
void detect_fused_kernel(const float* __restrict__ o13,
                         const float* __restrict__ o26,
                         const float* __restrict__ o52,
                         const float* __restrict__ a13,
                         const float* __restrict__ a26,
                         const float* __restrict__ a52,
                         const float* __restrict__ thr_p,
                         float* __restrict__ out)
{
    __shared__ unsigned           s_bm[BMW];
    __shared__ int                s_pc[BMW];
    __shared__ int                s_cnt;
    __shared__ unsigned long long s_keys[VCAP];
    __shared__ int                s_gidx[KDET];
    __shared__ unsigned           s_sup[KDET * RMAX];   // suppression bitmask rows
    __shared__ unsigned           s_keepw[RMAX];
    __shared__ float s_conf[KDET], s_ox[KDET], s_oy[KDET], s_w[KDET], s_h[KDET];
    __shared__ float s_cls[KDET], s_x1[KDET], s_y1[KDET], s_x2[KDET], s_y2[KDET], s_ar[KDET];

    const int n    = blockIdx.x;
    const int tid  = threadIdx.x;
    const int wid  = tid >> 5;
    const int lane = tid & 31;

    if (tid == 0) s_cnt = 0;
    for (int i = tid; i < BMW; i += NT) s_bm[i] = 0u;
    for (int i = tid; i < KDET * RMAX; i += NT) s_sup[i] = 0u;
    if (tid < RMAX) s_keepw[tid] = 0u;

    const float thr = *thr_p;

    // ================= phase 1: conf scan (max MLP: issue all loads first) =====
    // o13: 507 scalars; o26: 507 float4; o52: 2028 float4 (2 rounds)
    float  v13 = 0.f;  int g13base = -1;
    float4 v26 = make_float4(0,0,0,0); int g26base = -1;
    float4 v52a = make_float4(0,0,0,0); int g52abase = -1;
    float4 v52b = make_float4(0,0,0,0); int g52bbase = -1;

    if (tid < NB13) {
        const int a = tid / HW13, p = tid - a * HW13;
        v13 = o13[((size_t)n * 255 + a * 85) * HW13 + p];
        g13base = OFF13 + p * 3 + a;
    }
    if (tid < 3 * (HW26 / 4)) {               // 507
        const int a = tid / (HW26 / 4), q = tid - a * (HW26 / 4);
        v26 = ((const float4*)(o26 + ((size_t)n * 255 + a * 85) * HW26))[q];
        g26base = OFF26 + (4 * q) * 3 + a;    // step per c is 3
    }
    {
        const int a = tid / (HW52 / 4), q = tid - a * (HW52 / 4);   // tid<2028 always (a<2 for tid<1024... a = tid/676 <=1)
        v52a = ((const float4*)(o52 + ((size_t)n * 255 + a * 85) * HW52))[q];
        g52abase = OFF52 + (4 * q) * 3 + a;
    }
    {
        const int idx = tid + NT;
        if (idx < 3 * (HW52 / 4)) {           // 2028
            const int a = idx / (HW52 / 4), q = idx - a * (HW52 / 4);
            v52b = ((const float4*)(o52 + ((size_t)n * 255 + a * 85) * HW52))[q];
            g52bbase = OFF52 + (4 * q) * 3 + a;
        }
    }
    __syncthreads();   // init of s_bm/s_cnt complete (loads in flight already)

    // process
    {
        if (g13base >= 0 && v13 > thr) {
            unsigned long long key = ((unsigned long long)f2ord(v13) << 32)
                                   | (unsigned long long)(0xFFFFFFFFu - (unsigned)g13base);
            int pos = atomicAdd(&s_cnt, 1);
            if (pos < VCAP) s_keys[pos] = key;
            atomicOr(&s_bm[g13base >> 5], 1u << (g13base & 31));
        }
        #pragma unroll
        for (int c = 0; c < 4; c++) {
            float v = (c == 0) ? v26.x : (c == 1) ? v26.y : (c == 2) ? v26.z : v26.w;
            if (g26base >= 0 && v > thr) {
                int g = g26base + c * 3;
                unsigned long long key = ((unsigned long long)f2ord(v) << 32)
                                       | (unsigned long long)(0xFFFFFFFFu - (unsigned)g);
                int pos = atomicAdd(&s_cnt, 1);
                if (pos < VCAP) s_keys[pos] = key;
                atomicOr(&s_bm[g >> 5], 1u << (g & 31));
            }
        }
        #pragma unroll
        for (int c = 0; c < 4; c++) {
            float v = (c == 0) ? v52a.x : (c == 1) ? v52a.y : (c == 2) ? v52a.z : v52a.w;
            if (v > thr) {
                int g = g52abase + c * 3;
                unsigned long long key = ((unsigned long long)f2ord(v) << 32)
                                       | (unsigned long long)(0xFFFFFFFFu - (unsigned)g);
                int pos = atomicAdd(&s_cnt, 1);
                if (pos < VCAP) s_keys[pos] = key;
                atomicOr(&s_bm[g >> 5], 1u << (g & 31));
            }
        }
        #pragma unroll
        for (int c = 0; c < 4; c++) {
            float v = (c == 0) ? v52b.x : (c == 1) ? v52b.y : (c == 2) ? v52b.z : v52b.w;
            if (g52bbase >= 0 && v > thr) {
                int g = g52bbase + c * 3;
                unsigned long long key = ((unsigned long long)f2ord(v) << 32)
                                       | (unsigned long long)(0xFFFFFFFFu - (unsigned)g);
                int pos = atomicAdd(&s_cnt, 1);
                if (pos < VCAP) s_keys[pos] = key;
                atomicOr(&s_bm[g >> 5], 1u << (g & 31));
            }
        }
    }
    __syncthreads();

    int nv = s_cnt; if (nv > VCAP) nv = VCAP;
    const int take = (nv < KDET) ? nv : KDET;

    // ================= phase 2: rank sort (keys distinct) ======================
    if (tid < nv) {
        unsigned long long key = s_keys[tid];
        int rank = 0;
        for (int j = 0; j < nv; j++) rank += (s_keys[j] > key);
        if (rank < KDET)
            s_gidx[rank] = (int)(0xFFFFFFFFu - (unsigned)(key & 0xFFFFFFFFu));
    }

    // ================= phase 3: padding (parallel bitmap rank) =================
    for (int i = tid; i < BMW; i += NT) s_pc[i] = __popc(s_bm[i]);
    __syncthreads();
    if (wid == 0) {                         // chunked warp scan: 32 lanes × 11 words
        const int base = lane * 11;
        int sum = 0;
        #pragma unroll
        for (int k = 0; k < 11; k++) { int w = base + k; if (w < BMW) sum += s_pc[w]; }
        int incl = sum;
        #pragma unroll
        for (int off = 1; off < 32; off <<= 1) {
            int v = __shfl_up_sync(0xFFFFFFFFu, incl, off);
            if (lane >= off) incl += v;
        }
        int run = incl - sum;               // exclusive chunk base
        #pragma unroll
        for (int k = 0; k < 11; k++) {
            int w = base + k;
            if (w < BMW) { int t = s_pc[w]; s_pc[w] = run; run += t; }
        }
    }
    __syncthreads();
    const int need = KDET - take;
    if (need > 0) {
        int limit = KDET + nv; if (limit > NTOT) limit = NTOT;
        for (int idx = tid; idx < limit; idx += NT) {
            unsigned w = s_bm[idx >> 5], bit = 1u << (idx & 31);
            if (!(w & bit)) {
                int rank = idx - (s_pc[idx >> 5] + __popc(w & (bit - 1)));
                if (rank < need) s_gidx[take + rank] = idx;
            }
        }
    }
    __syncthreads();

    // ================= phase 4: decode only the valid `take` (warp/entry) ======
    for (int k = wid; k < take; k += (NT / 32)) {
        const int g = s_gidx[k];
        const float* o; const float* anch; int HW, W, bi; float stride;
        if (g < OFF26)      { o = o13; HW = HW13; W = 13; stride = 32.f; anch = a13; bi = g; }
        else if (g < OFF52) { o = o26; HW = HW26; W = 26; stride = 16.f; anch = a26; bi = g - OFF26; }
        else                { o = o52; HW = HW52; W = 52; stride =  8.f; anch = a52; bi = g - OFF52; }
        const int a = bi % 3;
        const int p = bi / 3;
        const int y = p / W;
        const int x = p - y * W;
        const float* base = o + ((size_t)n * 255 + a * 85) * HW + p;

        float head = (lane < 5) ? base[lane * HW] : 0.f;

        float best = -3.402823466e+38f; int bc = 0;
        #pragma unroll 1
        for (int c = lane; c < NCLS; c += 32) {
            float v = base[(5 + c) * HW];
            if (v > best) { best = v; bc = c; }
        }
        #pragma unroll
        for (int off = 16; off > 0; off >>= 1) {
            float vb = __shfl_down_sync(0xFFFFFFFFu, best, off);
            int   cb = __shfl_down_sync(0xFFFFFFFFu, bc,   off);
            if (vb > best || (vb == best && cb < bc)) { best = vb; bc = cb; }
        }

        const float conf = __shfl_sync(0xFFFFFFFFu, head, 0);
        const float tx   = __shfl_sync(0xFFFFFFFFu, head, 1);
        const float ty   = __shfl_sync(0xFFFFFFFFu, head, 2);
        const float tw   = __shfl_sync(0xFFFFFFFFu, head, 3);
        const float th   = __shfl_sync(0xFFFFFFFFu, head, 4);

        if (lane == 0) {
            const float ox = ((float)x + tx) * stride;
            const float oy = ((float)y + ty) * stride;
            const float w  = __expf(tw) * anch[a * 2 + 0];
            const float h  = __expf(th) * anch[a * 2 + 1];
            s_conf[k] = conf; s_ox[k] = ox; s_oy[k] = oy;
            s_w[k] = w; s_h[k] = h; s_cls[k] = (float)bc;
            const float x1 = ox - w * 0.5f, y1 = oy - h * 0.5f;
            const float x2 = ox + w * 0.5f, y2 = oy + h * 0.5f;
            s_x1[k] = x1; s_y1[k] = y1; s_x2[k] = x2; s_y2[k] = y2;
            s_ar[k] = (x2 - x1) * (y2 - y1);
        }
    }
    __syncthreads();

    // ================= phase 5a: parallel suppression matrix ===================
    const int R = (take + 31) >> 5;
    {
        const int total = take * take;
        for (int idx = tid; idx < total; idx += NT) {
            const int i = idx / take;
            const int j = idx - i * take;
            if (j < i && s_cls[i] == s_cls[j]) {
                float iw = fminf(s_x2[i], s_x2[j]) - fmaxf(s_x1[i], s_x1[j]);
                float ih = fminf(s_y2[i], s_y2[j]) - fmaxf(s_y1[i], s_y1[j]);
                float inter = fmaxf(iw, 0.f) * fmaxf(ih, 0.f);
                float uni = s_ar[i] + s_ar[j] - inter;
                if (inter / fmaxf(uni, 1e-9f) > 0.3f)
                    atomicOr(&s_sup[i * RMAX + (j >> 5)], 1u << (j & 31));
            }
        }
    }
    __syncthreads();

    // ================= phase 5b: greedy keep scan (warp 0, bitmask) ============
    if (wid == 0) {
        unsigned keepw = 0u;                 // lane l owns keep bits [32l, 32l+32)
        for (int i = 0; i < take; i++) {
            bool hit = (lane < R) && ((s_sup[i * RMAX + lane] & keepw) != 0u);
            bool sup = __any_sync(0xFFFFFFFFu, hit);
            if (!sup && lane == (i >> 5)) keepw |= (1u << (i & 31));
        }
        if (lane < RMAX) s_keepw[lane] = (lane < R) ? keepw : 0u;
    }
    __syncthreads();

    // ================= phase 6: coalesced output ===============================
    float* outn = out + (size_t)n * KDET * 7;
    for (int j = tid; j < KDET * 7; j += NT) {
        const int k = j / 7, c = j - k * 7;
        float v = 0.f;
        if (k < take && ((s_keepw[k >> 5] >> (k & 31)) & 1u)) {
            switch (c) {
                case 0: v = s_conf[k]; break;
                case 1: v = s_ox[k];   break;
                case 2: v = s_oy[k];   break;
                case 3: v = s_w[k];    break;
                case 4: v = s_h[k];    break;
                case 5: v = s_cls[k];  break;
                default: v = (float)n; break;
            }
        }
        outn[j] = v;
    }
}

extern "C" void kernel_launch(void* const* d_in, const int* in_sizes, int n_in,
                              void* d_out, int out_size)
{
    const float* o13 = (const float*)d_in[0];
    const float* o26 = (const float*)d_in[1];
    const float* o52 = (const float*)d_in[2];
    const float* a13 = (const float*)d_in[3];
    const float* a26 = (const float*)d_in[4];
    const float* a52 = (const float*)d_in[5];
    const float* thr = (const float*)d_in[6];
    float* out = (float*)d_out;

    detect_fused_kernel<<<NIMG, NT>>>(o13, o26, o52, a13, a26, a52, thr, out);
}

// round 11
// speedup vs baseline: 7.8750x; 1.1538x over previous
#include <cuda_runtime.h>
#include <cstdint>
#include <cfloat>

#define NIMG   64
#define KDET   300
#define NCLS   80
#define HW13   169
#define HW26   676
#define HW52   2704
#define NB13   (HW13*3)
#define NB26   (HW26*3)
#define NB52   (HW52*3)
#define OFF13  0
#define OFF26  NB13
#define OFF52  (NB13+NB26)
#define NTOT   (NB13+NB26+NB52)   // 10647
#define VCAP   1024
#define NT     1024
#define RMAX   10                 // ceil(KDET/32)

__device__ __forceinline__ unsigned f2ord(float f) {
    unsigned u = __float_as_uint(f);
    return (u & 0x80000000u) ? ~u : (u | 0x80000000u);
}

__global__ __launch_bounds__(NT, 1)
void detect_fused_kernel(const float* __restrict__ o13,
                         const float* __restrict__ o26,
                         const float* __restrict__ o52,
                         const float* __restrict__ a13,
                         const float* __restrict__ a26,
                         const float* __restrict__ a52,
                         const float* __restrict__ thr_p,
                         float* __restrict__ out)
{
    __shared__ int                s_cnt;
    __shared__ unsigned long long s_keys[VCAP];
    __shared__ int                s_gidx[KDET];
    __shared__ unsigned           s_sup[KDET * RMAX];
    __shared__ unsigned           s_keepw[RMAX];
    __shared__ int                s_flist[KDET];
    __shared__ float s_conf[KDET], s_ox[KDET], s_oy[KDET], s_w[KDET], s_h[KDET];
    __shared__ float s_cls[KDET], s_x1[KDET], s_y1[KDET], s_x2[KDET], s_y2[KDET], s_ar[KDET];

    const int n    = blockIdx.x;
    const int tid  = threadIdx.x;
    const int wid  = tid >> 5;
    const int lane = tid & 31;

    if (tid == 0) s_cnt = 0;
    for (int i = tid; i < KDET * RMAX; i += NT) s_sup[i] = 0u;
    if (tid < RMAX) s_keepw[tid] = 0u;

    const float thr = *thr_p;

    // ---- early zero-fill of this image's output (overlaps with scan loads) ----
    float* outn = out + (size_t)n * KDET * 7;          // 8400B, 16B-aligned
    {
        float4 z = make_float4(0.f, 0.f, 0.f, 0.f);
        if (tid < (KDET * 7) / 4) ((float4*)outn)[tid] = z;   // 525 stores
        if (tid == 0) outn[KDET * 7 - 1] = 0.f;               // 2100 not /4 -> is /4? 2100/4=525 exact
    }

    // ================= phase 1: conf scan (all loads issued first) =============
    float  v13 = 0.f;  int g13base = -1;
    float4 v26  = make_float4(0,0,0,0); int g26base  = -1;
    float4 v52a = make_float4(0,0,0,0); int g52abase = -1;
    float4 v52b = make_float4(0,0,0,0); int g52bbase = -1;

    if (tid < NB13) {
        const int a = tid / HW13, p = tid - a * HW13;
        v13 = o13[((size_t)n * 255 + a * 85) * HW13 + p];
        g13base = OFF13 + p * 3 + a;
    }
    if (tid < 3 * (HW26 / 4)) {               // 507
        const int a = tid / (HW26 / 4), q = tid - a * (HW26 / 4);
        v26 = ((const float4*)(o26 + ((size_t)n * 255 + a * 85) * HW26))[q];
        g26base = OFF26 + (4 * q) * 3 + a;
    }
    {
        const int a = tid / (HW52 / 4), q = tid - a * (HW52 / 4);
        v52a = ((const float4*)(o52 + ((size_t)n * 255 + a * 85) * HW52))[q];
        g52abase = OFF52 + (4 * q) * 3 + a;
    }
    {
        const int idx = tid + NT;
        if (idx < 3 * (HW52 / 4)) {           // 2028
            const int a = idx / (HW52 / 4), q = idx - a * (HW52 / 4);
            v52b = ((const float4*)(o52 + ((size_t)n * 255 + a * 85) * HW52))[q];
            g52bbase = OFF52 + (4 * q) * 3 + a;
        }
    }
    __syncthreads();   // s_cnt/s_sup init complete; loads already in flight

    #define EMIT(V, G) do { \
        if ((V) > thr) { \
            unsigned long long key = ((unsigned long long)f2ord(V) << 32) \
                                   | (unsigned long long)(0xFFFFFFFFu - (unsigned)(G)); \
            int pos = atomicAdd(&s_cnt, 1); \
            if (pos < VCAP) s_keys[pos] = key; \
        } } while (0)

    if (g13base >= 0) EMIT(v13, g13base);
    if (g26base >= 0) {
        EMIT(v26.x, g26base + 0); EMIT(v26.y, g26base + 3);
        EMIT(v26.z, g26base + 6); EMIT(v26.w, g26base + 9);
    }
    {
        EMIT(v52a.x, g52abase + 0); EMIT(v52a.y, g52abase + 3);
        EMIT(v52a.z, g52abase + 6); EMIT(v52a.w, g52abase + 9);
    }
    if (g52bbase >= 0) {
        EMIT(v52b.x, g52bbase + 0); EMIT(v52b.y, g52bbase + 3);
        EMIT(v52b.z, g52bbase + 6); EMIT(v52b.w, g52bbase + 9);
    }
    #undef EMIT
    __syncthreads();

    int nv = s_cnt; if (nv > VCAP) nv = VCAP;
    const int take = (nv < KDET) ? nv : KDET;

    // ================= phase 2: rank sort (keys distinct) ======================
    if (tid < nv) {
        unsigned long long key = s_keys[tid];
        int rank = 0;
        for (int j = 0; j < nv; j++) rank += (s_keys[j] > key);
        if (rank < KDET)
            s_gidx[rank] = (int)(0xFFFFFFFFu - (unsigned)(key & 0xFFFFFFFFu));
    }
    __syncthreads();

    // ================= phase 3: decode (batched loads, warp per entry) =========
    {
        float head_r[3], c0[3], c1[3], c2[3];
        int   g_r[3];
        bool  val_r[3];
        #pragma unroll
        for (int r = 0; r < 3; r++) {
            const int k = wid + r * 32;
            val_r[r] = (k < take);
            if (val_r[r]) {
                const int g = s_gidx[k];  g_r[r] = g;
                const float* o; int HW, bi;
                if (g < OFF26)      { o = o13; HW = HW13; bi = g; }
                else if (g < OFF52) { o = o26; HW = HW26; bi = g - OFF26; }
                else                { o = o52; HW = HW52; bi = g - OFF52; }
                const int a = bi % 3, p = bi / 3;
                const float* base = o + ((size_t)n * 255 + a * 85) * HW + p;
                head_r[r] = (lane < 5) ? base[lane * HW] : 0.f;
                c0[r] = base[(5 + lane) * HW];
                c1[r] = base[(37 + lane) * HW];
                c2[r] = (lane < 16) ? base[(69 + lane) * HW] : -FLT_MAX;
            }
        }
        #pragma unroll
        for (int r = 0; r < 3; r++) {
            if (!val_r[r]) continue;              // warp-uniform
            const int k = wid + r * 32;
            const int g = g_r[r];
            const float* anch; int W, bi; float stride;
            if (g < OFF26)      { W = 13; stride = 32.f; anch = a13; bi = g; }
            else if (g < OFF52) { W = 26; stride = 16.f; anch = a26; bi = g - OFF26; }
            else                { W = 52; stride =  8.f; anch = a52; bi = g - OFF52; }
            const int a = bi % 3, p = bi / 3;
            const int y = p / W, x = p - y * W;

            float best = c0[r]; int bc = lane;
            if (c1[r] > best)               { best = c1[r]; bc = lane + 32; }
            if (lane < 16 && c2[r] > best)  { best = c2[r]; bc = lane + 64; }
            #pragma unroll
            for (int off = 16; off > 0; off >>= 1) {
                float vb = __shfl_down_sync(0xFFFFFFFFu, best, off);
                int   cb = __shfl_down_sync(0xFFFFFFFFu, bc,   off);
                if (vb > best || (vb == best && cb < bc)) { best = vb; bc = cb; }
            }
            const float conf = __shfl_sync(0xFFFFFFFFu, head_r[r], 0);
            const float tx   = __shfl_sync(0xFFFFFFFFu, head_r[r], 1);
            const float ty   = __shfl_sync(0xFFFFFFFFu, head_r[r], 2);
            const float tw   = __shfl_sync(0xFFFFFFFFu, head_r[r], 3);
            const float th   = __shfl_sync(0xFFFFFFFFu, head_r[r], 4);
            if (lane == 0) {
                const float ox = ((float)x + tx) * stride;
                const float oy = ((float)y + ty) * stride;
                const float w  = __expf(tw) * anch[a * 2 + 0];
                const float h  = __expf(th) * anch[a * 2 + 1];
                s_conf[k] = conf; s_ox[k] = ox; s_oy[k] = oy;
                s_w[k] = w; s_h[k] = h; s_cls[k] = (float)bc;
                const float x1 = ox - w * 0.5f, y1 = oy - h * 0.5f;
                const float x2 = ox + w * 0.5f, y2 = oy + h * 0.5f;
                s_x1[k] = x1; s_y1[k] = y1; s_x2[k] = x2; s_y2[k] = y2;
                s_ar[k] = (x2 - x1) * (y2 - y1);
            }
        }
        // residual (take > 96: statistically negligible, but correct)
        for (int k = wid + 96; k < take; k += 32) {
            const int g = s_gidx[k];
            const float* o; const float* anch; int HW, W, bi; float stride;
            if (g < OFF26)      { o = o13; HW = HW13; W = 13; stride = 32.f; anch = a13; bi = g; }
            else if (g < OFF52) { o = o26; HW = HW26; W = 26; stride = 16.f; anch = a26; bi = g - OFF26; }
            else                { o = o52; HW = HW52; W = 52; stride =  8.f; anch = a52; bi = g - OFF52; }
            const int a = bi % 3, p = bi / 3;
            const int y = p / W, x = p - y * W;
            const float* base = o + ((size_t)n * 255 + a * 85) * HW + p;
            float head = (lane < 5) ? base[lane * HW] : 0.f;
            float best = -FLT_MAX; int bc = 0;
            for (int c = lane; c < NCLS; c += 32) {
                float v = base[(5 + c) * HW];
                if (v > best) { best = v; bc = c; }
            }
            #pragma unroll
            for (int off = 16; off > 0; off >>= 1) {
                float vb = __shfl_down_sync(0xFFFFFFFFu, best, off);
                int   cb = __shfl_down_sync(0xFFFFFFFFu, bc,   off);
                if (vb > best || (vb == best && cb < bc)) { best = vb; bc = cb; }
            }
            const float conf = __shfl_sync(0xFFFFFFFFu, head, 0);
            const float tx   = __shfl_sync(0xFFFFFFFFu, head, 1);
            const float ty   = __shfl_sync(0xFFFFFFFFu, head, 2);
            const float tw   = __shfl_sync(0xFFFFFFFFu, head, 3);
            const float th   = __shfl_sync(0xFFFFFFFFu, head, 4);
            if (lane == 0) {
                const float ox = ((float)x + tx) * stride;
                const float oy = ((float)y + ty) * stride;
                const float w  = __expf(tw) * anch[a * 2 + 0];
                const float h  = __expf(th) * anch[a * 2 + 1];
                s_conf[k] = conf; s_ox[k] = ox; s_oy[k] = oy;
                s_w[k] = w; s_h[k] = h; s_cls[k] = (float)bc;
                const float x1 = ox - w * 0.5f, y1 = oy - h * 0.5f;
                const float x2 = ox + w * 0.5f, y2 = oy + h * 0.5f;
                s_x1[k] = x1; s_y1[k] = y1; s_x2[k] = x2; s_y2[k] = y2;
                s_ar[k] = (x2 - x1) * (y2 - y1);
            }
        }
    }
    __syncthreads();

    // ================= phase 4: parallel suppression matrix ====================
    const int R = (take + 31) >> 5;
    {
        const int total = take * take;
        for (int idx = tid; idx < total; idx += NT) {
            const int i = idx / take;
            const int j = idx - i * take;
            if (j < i && s_cls[i] == s_cls[j]) {
                float iw = fminf(s_x2[i], s_x2[j]) - fmaxf(s_x1[i], s_x1[j]);
                float ih = fminf(s_y2[i], s_y2[j]) - fmaxf(s_y1[i], s_y1[j]);
                float inter = fmaxf(iw, 0.f) * fmaxf(ih, 0.f);
                float uni = s_ar[i] + s_ar[j] - inter;
                if (inter / fmaxf(uni, 1e-9f) > 0.3f)
                    atomicOr(&s_sup[i * RMAX + (j >> 5)], 1u << (j & 31));
            }
        }
    }
    __syncthreads();

    // ================= phase 5: greedy keep — conflict-free rows instant =======
    if (wid == 0) {
        int fcnt = 0;
        for (int base = 0; base < take; base += 32) {
            const int i = base + lane;
            bool any = false;
            if (i < take) {
                #pragma unroll
                for (int w = 0; w < RMAX; w++)
                    if (w < R) any |= (s_sup[i * RMAX + w] != 0u);
            }
            const unsigned flg  = __ballot_sync(0xFFFFFFFFu, any);
            const unsigned actv = __ballot_sync(0xFFFFFFFFu, i < take);
            if (lane == 0) s_keepw[base >> 5] = actv & ~flg;   // rows w/o predecessors: kept
            if (any) {
                int pos = fcnt + __popc(flg & ((1u << lane) - 1u));
                s_flist[pos] = i;
            }
            fcnt += __popc(flg);
        }
        __syncwarp();
        for (int f = 0; f < fcnt; f++) {
            const int i = s_flist[f];
            bool hit = (lane < R) && ((s_sup[i * RMAX + lane] & s_keepw[lane]) != 0u);
            bool sup = __any_sync(0xFFFFFFFFu, hit);
            if (lane == (i >> 5)) {
                unsigned w = s_keepw[lane];
                s_keepw[lane] = sup ? (w & ~(1u << (i & 31))) : (w | (1u << (i & 31)));
            }
            __syncwarp();
        }
    }
    __syncthreads();

    // ================= phase 6: write only kept rows (rest already zero) =======
    for (int j = tid; j < take * 7; j += NT) {
        const int k = j / 7, c = j - k * 7;
        if ((s_keepw[k >> 5] >> (k & 31)) & 1u) {
            float v;
            switch (c) {
                case 0: v = s_conf[k]; break;
                case 1: v = s_ox[k];   break;
                case 2: v = s_oy[k];   break;
                case 3: v = s_w[k];    break;
                case 4: v = s_h[k];    break;
                case 5: v = s_cls[k];  break;
                default: v = (float)n; break;
            }
            outn[j] = v;
        }
    }
}

extern "C" void kernel_launch(void* const* d_in, const int* in_sizes, int n_in,
                              void* d_out, int out_size)
{
    const float* o13 = (const float*)d_in[0];
    const float* o26 = (const float*)d_in[1];
    const float* o52 = (const float*)d_in[2];
    const float* a13 = (const float*)d_in[3];
    const float* a26 = (const float*)d_in[4];
    const float* a52 = (const float*)d_in[5];
    const float* thr = (const float*)d_in[6];
    float* out = (float*)d_out;

    detect_fused_kernel<<<NIMG, NT>>>(o13, o26, o52, a13, a26, a52, thr, out);
}